// round 4
// baseline (speedup 1.0000x reference)
#include <cuda_runtime.h>
#include <math.h>
#include <stdint.h>

// Problem dims (fixed by the reference)
#define BDIM 64
#define TDIM 512
#define HDIM 1024
#define KQ   49
#define MT_ROWS (BDIM*TDIM)   // 32768

// ---------------- static scratch (no allocs allowed) ----------------
__device__ float g_st[33554432];        // s_t  [B*T, H]   (128 MB)
__device__ float g_g [MT_ROWS * 64];    // g    [B*T, 49] padded to 64
__device__ float g_cs[MT_ROWS * 64];    // content_s raw (s_t@Ws^T)
__device__ float g_cv[3200 * 64];       // cv   [B*49, 49] padded rows/cols
__device__ float g_al[MT_ROWS * 64];    // alpha [B*T, 49] padded
__device__ float g_be[MT_ROWS];         // beta  [B*T]

// ---------------- tf32 helpers ----------------
__device__ __forceinline__ unsigned f2tf32(float x){
    unsigned u; asm("cvt.rna.tf32.f32 %0, %1;" : "=r"(u) : "f"(x)); return u;
}
__device__ __forceinline__ void mma_tf32(float c[4],
        unsigned a0, unsigned a1, unsigned a2, unsigned a3,
        unsigned b0, unsigned b1){
    asm volatile(
        "mma.sync.aligned.m16n8k8.row.col.f32.tf32.tf32.f32 "
        "{%0,%1,%2,%3}, {%4,%5,%6,%7}, {%8,%9}, {%0,%1,%2,%3};\n"
        : "+f"(c[0]), "+f"(c[1]), "+f"(c[2]), "+f"(c[3])
        : "r"(a0), "r"(a1), "r"(a2), "r"(a3), "r"(b0), "r"(b1));
}

// ---------------- tf32 GEMM: out[m,n] = sum_k A[m,k]*Bm[n,k] ----------------
// Block tile 128x64, BK=16, 8 warps (4x2), warp tile 32x32 (2x4 m16n8 frags).
// EPI==0 : out = sigmoid(acc) * tanh(cells)   (s_t path, exact tiles, ld=HDIM)
// EPI==1 : out[m*ldout+n] = acc, guarded by Mreal/Nreal
template<int EPI>
__global__ void __launch_bounds__(256, 2)
gemm_tf32_kernel(const float* __restrict__ A, const float* __restrict__ Bm,
                 const float* __restrict__ cells, float* __restrict__ out,
                 int Mreal, int Nreal, int ldout)
{
    __shared__ __align__(16) float As[128][20];  // stride 20 -> conflict-free frags
    __shared__ __align__(16) float Bs[64][20];

    const int tid  = threadIdx.x;
    const int lane = tid & 31;
    const int warp = tid >> 5;
    const int grp  = lane >> 2;     // 0..7
    const int qid  = lane & 3;      // 0..3
    const int wm   = warp >> 1;     // 0..3
    const int wn   = warp & 1;      // 0..1

    const int m0 = blockIdx.y * 128;
    const int n0 = blockIdx.x * 64;

    const int lrow = tid >> 2;      // 0..63
    const int lq   = tid & 3;

    float c[2][4][4];
    #pragma unroll
    for (int i = 0; i < 2; i++)
        #pragma unroll
        for (int j = 0; j < 4; j++)
            #pragma unroll
            for (int r = 0; r < 4; r++) c[i][j][r] = 0.f;

    for (int k0 = 0; k0 < HDIM; k0 += 16) {
        // ---- global -> smem (convert to tf32 once) ----
        #pragma unroll
        for (int half = 0; half < 2; half++) {
            int r = lrow + half * 64;
            int m = m0 + r;
            float4 v = make_float4(0.f, 0.f, 0.f, 0.f);
            if (m < Mreal)
                v = *(const float4*)(A + (size_t)m * HDIM + k0 + lq * 4);
            unsigned* dst = (unsigned*)&As[r][lq * 4];
            dst[0] = f2tf32(v.x); dst[1] = f2tf32(v.y);
            dst[2] = f2tf32(v.z); dst[3] = f2tf32(v.w);
        }
        {
            int n = n0 + lrow;
            float4 v = make_float4(0.f, 0.f, 0.f, 0.f);
            if (n < Nreal)
                v = *(const float4*)(Bm + (size_t)n * HDIM + k0 + lq * 4);
            unsigned* dst = (unsigned*)&Bs[lrow][lq * 4];
            dst[0] = f2tf32(v.x); dst[1] = f2tf32(v.y);
            dst[2] = f2tf32(v.z); dst[3] = f2tf32(v.w);
        }
        __syncthreads();

        // ---- two k8 steps ----
        #pragma unroll
        for (int kk = 0; kk < 2; kk++) {
            unsigned a[2][4], b[4][2];
            #pragma unroll
            for (int mt = 0; mt < 2; mt++) {
                int rb = wm * 32 + mt * 16 + grp;
                a[mt][0] = __float_as_uint(As[rb    ][kk * 8 + qid    ]);
                a[mt][1] = __float_as_uint(As[rb + 8][kk * 8 + qid    ]);
                a[mt][2] = __float_as_uint(As[rb    ][kk * 8 + qid + 4]);
                a[mt][3] = __float_as_uint(As[rb + 8][kk * 8 + qid + 4]);
            }
            #pragma unroll
            for (int nt = 0; nt < 4; nt++) {
                int nb = wn * 32 + nt * 8 + grp;
                b[nt][0] = __float_as_uint(Bs[nb][kk * 8 + qid    ]);
                b[nt][1] = __float_as_uint(Bs[nb][kk * 8 + qid + 4]);
            }
            #pragma unroll
            for (int mt = 0; mt < 2; mt++)
                #pragma unroll
                for (int nt = 0; nt < 4; nt++)
                    mma_tf32(c[mt][nt], a[mt][0], a[mt][1], a[mt][2], a[mt][3],
                             b[nt][0], b[nt][1]);
        }
        __syncthreads();
    }

    // ---- epilogue ----
    #pragma unroll
    for (int mt = 0; mt < 2; mt++) {
        #pragma unroll
        for (int nt = 0; nt < 4; nt++) {
            int m = m0 + wm * 32 + mt * 16 + grp;
            int n = n0 + wn * 32 + nt * 8 + qid * 2;
            #pragma unroll
            for (int half = 0; half < 2; half++) {
                int mm = m + half * 8;
                float v0 = c[mt][nt][half * 2 + 0];
                float v1 = c[mt][nt][half * 2 + 1];
                if (EPI == 0) {
                    size_t idx = (size_t)mm * HDIM + n;
                    float2 cl = *(const float2*)(cells + idx);
                    float s0 = 1.f / (1.f + expf(-v0));
                    float s1 = 1.f / (1.f + expf(-v1));
                    float2 o;
                    o.x = s0 * tanhf(cl.x);
                    o.y = s1 * tanhf(cl.y);
                    *(float2*)(out + idx) = o;
                } else {
                    if (mm < Mreal) {
                        size_t row = (size_t)mm * ldout;
                        if (n     < Nreal) out[row + n    ] = v0;
                        if (n + 1 < Nreal) out[row + n + 1] = v1;
                    }
                }
            }
        }
    }
}

// ---------------- attention logits: alpha, beta per (b,t) ----------------
__global__ void __launch_bounds__(64)
attn_logits_kernel(const float* __restrict__ Wh)
{
    const int t  = blockIdx.x;
    const int b  = blockIdx.y;
    const int bt = b * TDIM + t;
    const int tid = threadIdx.x;

    __shared__ float cvsh[KQ * KQ];
    __shared__ float gsh[KQ], cssh[KQ], whsh[64];
    __shared__ float zsh[64], red[64];

    for (int i = tid; i < KQ * KQ; i += 64) {
        int k = i / KQ, j = i - k * KQ;
        cvsh[i] = g_cv[(size_t)(b * KQ + k) * 64 + j];
    }
    if (tid < KQ) {
        gsh[tid]  = g_g [(size_t)bt * 64 + tid];
        cssh[tid] = g_cs[(size_t)bt * 64 + tid];
    }
    whsh[tid] = (tid < KQ) ? Wh[tid] : 0.f;
    __syncthreads();

    // z_ext = sum_j tanh(cs_j + g_j) * Wh_j
    float e = 0.f;
    if (tid < KQ) e = tanhf(cssh[tid] + gsh[tid]) * whsh[tid];
    red[tid] = e;
    __syncthreads();
    for (int s = 32; s > 0; s >>= 1) {
        if (tid < s) red[tid] += red[tid + s];
        __syncthreads();
    }
    float zx = red[0];
    __syncthreads();

    // z_k = sum_j tanh(cv[b,k,j] + g_j) * Wh_j
    float z = -1e30f;
    if (tid < KQ) {
        float acc = 0.f;
        const float* cvr = &cvsh[tid * KQ];
        #pragma unroll 7
        for (int j = 0; j < KQ; j++)
            acc += tanhf(cvr[j] + gsh[j]) * whsh[j];
        z = acc;
    }
    zsh[tid] = z;
    red[tid] = z;
    __syncthreads();
    for (int s = 32; s > 0; s >>= 1) {
        if (tid < s) red[tid] = fmaxf(red[tid], red[tid + s]);
        __syncthreads();
    }
    float mx = red[0];
    __syncthreads();

    float ez = (tid < KQ) ? expf(zsh[tid] - mx) : 0.f;
    red[tid] = ez;
    __syncthreads();
    for (int s = 32; s > 0; s >>= 1) {
        if (tid < s) red[tid] += red[tid + s];
        __syncthreads();
    }
    float sum49 = red[0];

    if (tid < KQ) g_al[(size_t)bt * 64 + tid] = ez / sum49;
    if (tid == 0) {
        float M2 = fmaxf(mx, zx);
        float denom = expf(mx - M2) * sum49 + expf(zx - M2);
        g_be[bt] = expf(zx - M2) / denom;
    }
}

// ---------------- final: out = beta*s_t + (1-beta)*(alpha@V) + hiddens ------
__global__ void __launch_bounds__(256)
final_kernel(const float* __restrict__ V, const float* __restrict__ hiddens,
             float* __restrict__ out)
{
    const int b  = blockIdx.z;
    const int t0 = blockIdx.y * 16;
    const int h0 = blockIdx.x * 256;
    const int tid  = threadIdx.x;
    const int hthr = tid & 63;      // 64 h-groups of 4
    const int tthr = tid >> 6;      // 4 t-groups of 4

    __shared__ float al[16][52];
    __shared__ float be[16];

    for (int i = tid; i < 16 * KQ; i += 256) {
        int tt = i / KQ, k = i - tt * KQ;
        al[tt][k] = g_al[(size_t)(b * TDIM + t0 + tt) * 64 + k];
    }
    if (tid < 16) be[tid] = g_be[b * TDIM + t0 + tid];
    __syncthreads();

    const int h = h0 + hthr * 4;
    float4 acc[4];
    #pragma unroll
    for (int i = 0; i < 4; i++) acc[i] = make_float4(0.f, 0.f, 0.f, 0.f);

    const float* Vb = V + (size_t)b * KQ * HDIM + h;
    for (int k = 0; k < KQ; k++) {
        float4 v = *(const float4*)(Vb + (size_t)k * HDIM);
        #pragma unroll
        for (int i = 0; i < 4; i++) {
            float a = al[tthr * 4 + i][k];
            acc[i].x += a * v.x; acc[i].y += a * v.y;
            acc[i].z += a * v.z; acc[i].w += a * v.w;
        }
    }
    #pragma unroll
    for (int i = 0; i < 4; i++) {
        int t = t0 + tthr * 4 + i;
        size_t idx = ((size_t)(b * TDIM + t)) * HDIM + h;
        float4 s  = *(const float4*)(g_st + idx);
        float4 hd = *(const float4*)(hiddens + idx);
        float bt = be[tthr * 4 + i];
        float om = 1.f - bt;
        float4 o;
        o.x = bt * s.x + om * acc[i].x + hd.x;
        o.y = bt * s.y + om * acc[i].y + hd.y;
        o.z = bt * s.z + om * acc[i].z + hd.z;
        o.w = bt * s.w + om * acc[i].w + hd.w;
        *(float4*)(out + idx) = o;
    }
}

// ---------------- launch ----------------
extern "C" void kernel_launch(void* const* d_in, const int* in_sizes, int n_in,
                              void* d_out, int out_size)
{
    const float* x       = (const float*)d_in[0];
    const float* hiddens = (const float*)d_in[1];
    const float* cells   = (const float*)d_in[2];
    const float* V       = (const float*)d_in[3];
    const float* Wx      = (const float*)d_in[4];
    // d_in[5] = Whh, unused: h_prev == 0 so its contribution is exactly zero.
    const float* Wv      = (const float*)d_in[6];
    const float* Wg      = (const float*)d_in[7];
    const float* Ws      = (const float*)d_in[8];
    const float* Wh      = (const float*)d_in[9];
    float* out = (float*)d_out;

    float *p_st, *p_g, *p_cs, *p_cv;
    cudaGetSymbolAddress((void**)&p_st, g_st);
    cudaGetSymbolAddress((void**)&p_g,  g_g);
    cudaGetSymbolAddress((void**)&p_cs, g_cs);
    cudaGetSymbolAddress((void**)&p_cv, g_cv);

    // s_t = sigmoid(x @ Wx^T) * tanh(cells)       [32768 x 1024]
    gemm_tf32_kernel<0><<<dim3(16, 256), 256>>>(x, Wx, cells, p_st,
                                                MT_ROWS, HDIM, HDIM);
    // g = hiddens @ Wg^T                          [32768 x 49]
    gemm_tf32_kernel<1><<<dim3(1, 256), 256>>>(hiddens, Wg, nullptr, p_g,
                                               MT_ROWS, KQ, 64);
    // cs = s_t @ Ws^T                             [32768 x 49] (after s_t)
    gemm_tf32_kernel<1><<<dim3(1, 256), 256>>>(p_st, Ws, nullptr, p_cs,
                                               MT_ROWS, KQ, 64);
    // cv = V @ Wv^T  (V viewed as [B*49, 1024])   [3136 x 49]
    gemm_tf32_kernel<1><<<dim3(1, 25), 256>>>(V, Wv, nullptr, p_cv,
                                              3136, KQ, 64);
    // alpha / beta per (b,t)
    attn_logits_kernel<<<dim3(TDIM, BDIM), 64>>>(Wh);
    // out = beta*s_t + (1-beta)*(alpha@V) + hiddens
    final_kernel<<<dim3(4, 32, 64), 256>>>(V, hiddens, out);
}

// round 5
// speedup vs baseline: 1.0020x; 1.0020x over previous
#include <cuda_runtime.h>
#include <math.h>
#include <stdint.h>

// Problem dims (fixed by the reference)
#define BDIM 64
#define TDIM 512
#define HDIM 1024
#define KQ   49
#define MT_ROWS (BDIM*TDIM)   // 32768

// ---------------- static scratch (no allocs allowed) ----------------
__device__ float g_st[33554432];        // s_t  [B*T, H]   (128 MB)
__device__ float g_g [MT_ROWS * 64];    // g    [B*T, 49] padded to 64
__device__ float g_cs[MT_ROWS * 64];    // content_s raw (s_t@Ws^T)
__device__ float g_cv[3200 * 64];       // cv   [B*49, 49] padded rows/cols
__device__ float g_al[MT_ROWS * 64];    // alpha [B*T, 49] padded
__device__ float g_be[MT_ROWS];         // beta  [B*T]

// ---------------- tf32 helpers ----------------
__device__ __forceinline__ unsigned f2tf32(float x){
    unsigned u; asm("cvt.rna.tf32.f32 %0, %1;" : "=r"(u) : "f"(x)); return u;
}
__device__ __forceinline__ void mma_tf32(float c[4],
        unsigned a0, unsigned a1, unsigned a2, unsigned a3,
        unsigned b0, unsigned b1){
    asm volatile(
        "mma.sync.aligned.m16n8k8.row.col.f32.tf32.tf32.f32 "
        "{%0,%1,%2,%3}, {%4,%5,%6,%7}, {%8,%9}, {%0,%1,%2,%3};\n"
        : "+f"(c[0]), "+f"(c[1]), "+f"(c[2]), "+f"(c[3])
        : "r"(a0), "r"(a1), "r"(a2), "r"(a3), "r"(b0), "r"(b1));
}

// ---------------- tf32 GEMM: out[m,n] = sum_k A[m,k]*Bm[n,k] ----------------
// Block tile 128x64, BK=16, 8 warps (4x2), warp tile 32x32 (2x4 m16n8 frags).
// EPI==0 : out = sigmoid(acc) * tanh(cells)   (s_t path, exact tiles, ld=HDIM)
// EPI==1 : out[m*ldout+n] = acc, guarded by Mreal/Nreal
template<int EPI>
__global__ void __launch_bounds__(256, 2)
gemm_tf32_kernel(const float* __restrict__ A, const float* __restrict__ Bm,
                 const float* __restrict__ cells, float* __restrict__ out,
                 int Mreal, int Nreal, int ldout)
{
    __shared__ __align__(16) float As[128][20];  // stride 20 -> conflict-free frags
    __shared__ __align__(16) float Bs[64][20];

    const int tid  = threadIdx.x;
    const int lane = tid & 31;
    const int warp = tid >> 5;
    const int grp  = lane >> 2;     // 0..7
    const int qid  = lane & 3;      // 0..3
    const int wm   = warp >> 1;     // 0..3
    const int wn   = warp & 1;      // 0..1

    const int m0 = blockIdx.y * 128;
    const int n0 = blockIdx.x * 64;

    const int lrow = tid >> 2;      // 0..63
    const int lq   = tid & 3;

    float c[2][4][4];
    #pragma unroll
    for (int i = 0; i < 2; i++)
        #pragma unroll
        for (int j = 0; j < 4; j++)
            #pragma unroll
            for (int r = 0; r < 4; r++) c[i][j][r] = 0.f;

    for (int k0 = 0; k0 < HDIM; k0 += 16) {
        // ---- global -> smem (convert to tf32 once) ----
        #pragma unroll
        for (int half = 0; half < 2; half++) {
            int r = lrow + half * 64;
            int m = m0 + r;
            float4 v = make_float4(0.f, 0.f, 0.f, 0.f);
            if (m < Mreal)
                v = *(const float4*)(A + (size_t)m * HDIM + k0 + lq * 4);
            unsigned* dst = (unsigned*)&As[r][lq * 4];
            dst[0] = f2tf32(v.x); dst[1] = f2tf32(v.y);
            dst[2] = f2tf32(v.z); dst[3] = f2tf32(v.w);
        }
        {
            int n = n0 + lrow;
            float4 v = make_float4(0.f, 0.f, 0.f, 0.f);
            if (n < Nreal)
                v = *(const float4*)(Bm + (size_t)n * HDIM + k0 + lq * 4);
            unsigned* dst = (unsigned*)&Bs[lrow][lq * 4];
            dst[0] = f2tf32(v.x); dst[1] = f2tf32(v.y);
            dst[2] = f2tf32(v.z); dst[3] = f2tf32(v.w);
        }
        __syncthreads();

        // ---- two k8 steps ----
        #pragma unroll
        for (int kk = 0; kk < 2; kk++) {
            unsigned a[2][4], b[4][2];
            #pragma unroll
            for (int mt = 0; mt < 2; mt++) {
                int rb = wm * 32 + mt * 16 + grp;
                a[mt][0] = __float_as_uint(As[rb    ][kk * 8 + qid    ]);
                a[mt][1] = __float_as_uint(As[rb + 8][kk * 8 + qid    ]);
                a[mt][2] = __float_as_uint(As[rb    ][kk * 8 + qid + 4]);
                a[mt][3] = __float_as_uint(As[rb + 8][kk * 8 + qid + 4]);
            }
            #pragma unroll
            for (int nt = 0; nt < 4; nt++) {
                int nb = wn * 32 + nt * 8 + grp;
                b[nt][0] = __float_as_uint(Bs[nb][kk * 8 + qid    ]);
                b[nt][1] = __float_as_uint(Bs[nb][kk * 8 + qid + 4]);
            }
            #pragma unroll
            for (int mt = 0; mt < 2; mt++)
                #pragma unroll
                for (int nt = 0; nt < 4; nt++)
                    mma_tf32(c[mt][nt], a[mt][0], a[mt][1], a[mt][2], a[mt][3],
                             b[nt][0], b[nt][1]);
        }
        __syncthreads();
    }

    // ---- epilogue ----
    #pragma unroll
    for (int mt = 0; mt < 2; mt++) {
        #pragma unroll
        for (int nt = 0; nt < 4; nt++) {
            int m = m0 + wm * 32 + mt * 16 + grp;
            int n = n0 + wn * 32 + nt * 8 + qid * 2;
            #pragma unroll
            for (int half = 0; half < 2; half++) {
                int mm = m + half * 8;
                float v0 = c[mt][nt][half * 2 + 0];
                float v1 = c[mt][nt][half * 2 + 1];
                if (EPI == 0) {
                    size_t idx = (size_t)mm * HDIM + n;
                    float2 cl = *(const float2*)(cells + idx);
                    float s0 = 1.f / (1.f + expf(-v0));
                    float s1 = 1.f / (1.f + expf(-v1));
                    float2 o;
                    o.x = s0 * tanhf(cl.x);
                    o.y = s1 * tanhf(cl.y);
                    *(float2*)(out + idx) = o;
                } else {
                    if (mm < Mreal) {
                        size_t row = (size_t)mm * ldout;
                        if (n     < Nreal) out[row + n    ] = v0;
                        if (n + 1 < Nreal) out[row + n + 1] = v1;
                    }
                }
            }
        }
    }
}

// ---------------- attention logits: alpha, beta per (b,t) ----------------
__global__ void __launch_bounds__(64)
attn_logits_kernel(const float* __restrict__ Wh)
{
    const int t  = blockIdx.x;
    const int b  = blockIdx.y;
    const int bt = b * TDIM + t;
    const int tid = threadIdx.x;

    __shared__ float cvsh[KQ * KQ];
    __shared__ float gsh[KQ], cssh[KQ], whsh[64];
    __shared__ float zsh[64], red[64];

    for (int i = tid; i < KQ * KQ; i += 64) {
        int k = i / KQ, j = i - k * KQ;
        cvsh[i] = g_cv[(size_t)(b * KQ + k) * 64 + j];
    }
    if (tid < KQ) {
        gsh[tid]  = g_g [(size_t)bt * 64 + tid];
        cssh[tid] = g_cs[(size_t)bt * 64 + tid];
    }
    whsh[tid] = (tid < KQ) ? Wh[tid] : 0.f;
    __syncthreads();

    // z_ext = sum_j tanh(cs_j + g_j) * Wh_j
    float e = 0.f;
    if (tid < KQ) e = tanhf(cssh[tid] + gsh[tid]) * whsh[tid];
    red[tid] = e;
    __syncthreads();
    for (int s = 32; s > 0; s >>= 1) {
        if (tid < s) red[tid] += red[tid + s];
        __syncthreads();
    }
    float zx = red[0];
    __syncthreads();

    // z_k = sum_j tanh(cv[b,k,j] + g_j) * Wh_j
    float z = -1e30f;
    if (tid < KQ) {
        float acc = 0.f;
        const float* cvr = &cvsh[tid * KQ];
        #pragma unroll 7
        for (int j = 0; j < KQ; j++)
            acc += tanhf(cvr[j] + gsh[j]) * whsh[j];
        z = acc;
    }
    zsh[tid] = z;
    red[tid] = z;
    __syncthreads();
    for (int s = 32; s > 0; s >>= 1) {
        if (tid < s) red[tid] = fmaxf(red[tid], red[tid + s]);
        __syncthreads();
    }
    float mx = red[0];
    __syncthreads();

    float ez = (tid < KQ) ? expf(zsh[tid] - mx) : 0.f;
    red[tid] = ez;
    __syncthreads();
    for (int s = 32; s > 0; s >>= 1) {
        if (tid < s) red[tid] += red[tid + s];
        __syncthreads();
    }
    float sum49 = red[0];

    if (tid < KQ) g_al[(size_t)bt * 64 + tid] = ez / sum49;
    if (tid == 0) {
        float M2 = fmaxf(mx, zx);
        float denom = expf(mx - M2) * sum49 + expf(zx - M2);
        g_be[bt] = expf(zx - M2) / denom;
    }
}

// ---------------- final: out = beta*s_t + (1-beta)*(alpha@V) + hiddens ------
__global__ void __launch_bounds__(256)
final_kernel(const float* __restrict__ V, const float* __restrict__ hiddens,
             float* __restrict__ out)
{
    const int b  = blockIdx.z;
    const int t0 = blockIdx.y * 16;
    const int h0 = blockIdx.x * 256;
    const int tid  = threadIdx.x;
    const int hthr = tid & 63;      // 64 h-groups of 4
    const int tthr = tid >> 6;      // 4 t-groups of 4

    __shared__ float al[16][52];
    __shared__ float be[16];

    for (int i = tid; i < 16 * KQ; i += 256) {
        int tt = i / KQ, k = i - tt * KQ;
        al[tt][k] = g_al[(size_t)(b * TDIM + t0 + tt) * 64 + k];
    }
    if (tid < 16) be[tid] = g_be[b * TDIM + t0 + tid];
    __syncthreads();

    const int h = h0 + hthr * 4;
    float4 acc[4];
    #pragma unroll
    for (int i = 0; i < 4; i++) acc[i] = make_float4(0.f, 0.f, 0.f, 0.f);

    const float* Vb = V + (size_t)b * KQ * HDIM + h;
    for (int k = 0; k < KQ; k++) {
        float4 v = *(const float4*)(Vb + (size_t)k * HDIM);
        #pragma unroll
        for (int i = 0; i < 4; i++) {
            float a = al[tthr * 4 + i][k];
            acc[i].x += a * v.x; acc[i].y += a * v.y;
            acc[i].z += a * v.z; acc[i].w += a * v.w;
        }
    }
    #pragma unroll
    for (int i = 0; i < 4; i++) {
        int t = t0 + tthr * 4 + i;
        size_t idx = ((size_t)(b * TDIM + t)) * HDIM + h;
        float4 s  = *(const float4*)(g_st + idx);
        float4 hd = *(const float4*)(hiddens + idx);
        float bt = be[tthr * 4 + i];
        float om = 1.f - bt;
        float4 o;
        o.x = bt * s.x + om * acc[i].x + hd.x;
        o.y = bt * s.y + om * acc[i].y + hd.y;
        o.z = bt * s.z + om * acc[i].z + hd.z;
        o.w = bt * s.w + om * acc[i].w + hd.w;
        *(float4*)(out + idx) = o;
    }
}

// ---------------- launch ----------------
extern "C" void kernel_launch(void* const* d_in, const int* in_sizes, int n_in,
                              void* d_out, int out_size)
{
    const float* x       = (const float*)d_in[0];
    const float* hiddens = (const float*)d_in[1];
    const float* cells   = (const float*)d_in[2];
    const float* V       = (const float*)d_in[3];
    const float* Wx      = (const float*)d_in[4];
    // d_in[5] = Whh, unused: h_prev == 0 so its contribution is exactly zero.
    const float* Wv      = (const float*)d_in[6];
    const float* Wg      = (const float*)d_in[7];
    const float* Ws      = (const float*)d_in[8];
    const float* Wh      = (const float*)d_in[9];
    float* out = (float*)d_out;

    float *p_st, *p_g, *p_cs, *p_cv;
    cudaGetSymbolAddress((void**)&p_st, g_st);
    cudaGetSymbolAddress((void**)&p_g,  g_g);
    cudaGetSymbolAddress((void**)&p_cs, g_cs);
    cudaGetSymbolAddress((void**)&p_cv, g_cv);

    // s_t = sigmoid(x @ Wx^T) * tanh(cells)       [32768 x 1024]
    gemm_tf32_kernel<0><<<dim3(16, 256), 256>>>(x, Wx, cells, p_st,
                                                MT_ROWS, HDIM, HDIM);
    // g = hiddens @ Wg^T                          [32768 x 49]
    gemm_tf32_kernel<1><<<dim3(1, 256), 256>>>(hiddens, Wg, nullptr, p_g,
                                               MT_ROWS, KQ, 64);
    // cs = s_t @ Ws^T                             [32768 x 49] (after s_t)
    gemm_tf32_kernel<1><<<dim3(1, 256), 256>>>(p_st, Ws, nullptr, p_cs,
                                               MT_ROWS, KQ, 64);
    // cv = V @ Wv^T  (V viewed as [B*49, 1024])   [3136 x 49]
    gemm_tf32_kernel<1><<<dim3(1, 25), 256>>>(V, Wv, nullptr, p_cv,
                                              3136, KQ, 64);
    // alpha / beta per (b,t)
    attn_logits_kernel<<<dim3(TDIM, BDIM), 64>>>(Wh);
    // out = beta*s_t + (1-beta)*(alpha@V) + hiddens
    final_kernel<<<dim3(4, 32, 64), 256>>>(V, hiddens, out);
}

// round 6
// speedup vs baseline: 1.0035x; 1.0015x over previous
#include <cuda_runtime.h>
#include <math.h>
#include <stdint.h>

// Problem dims (fixed by the reference)
#define BDIM 64
#define TDIM 512
#define HDIM 1024
#define KQ   49
#define MT_ROWS (BDIM*TDIM)   // 32768

// ---------------- static scratch (no allocs allowed) ----------------
__device__ float g_st[33554432];        // s_t  [B*T, H]   (128 MB)
__device__ float g_g [MT_ROWS * 64];    // g    [B*T, 49] padded to 64
__device__ float g_cs[MT_ROWS * 64];    // content_s raw (s_t@Ws^T)
__device__ float g_cv[3200 * 64];       // cv   [B*49, 49] padded rows/cols
__device__ float g_al[MT_ROWS * 64];    // alpha [B*T, 49] padded
__device__ float g_be[MT_ROWS];         // beta  [B*T]

// ---------------- tf32 helpers ----------------
__device__ __forceinline__ unsigned f2tf32(float x){
    unsigned u; asm("cvt.rna.tf32.f32 %0, %1;" : "=r"(u) : "f"(x)); return u;
}
__device__ __forceinline__ void mma_tf32(float c[4],
        unsigned a0, unsigned a1, unsigned a2, unsigned a3,
        unsigned b0, unsigned b1){
    asm volatile(
        "mma.sync.aligned.m16n8k8.row.col.f32.tf32.tf32.f32 "
        "{%0,%1,%2,%3}, {%4,%5,%6,%7}, {%8,%9}, {%0,%1,%2,%3};\n"
        : "+f"(c[0]), "+f"(c[1]), "+f"(c[2]), "+f"(c[3])
        : "r"(a0), "r"(a1), "r"(a2), "r"(a3), "r"(b0), "r"(b1));
}

// ---------------- tf32 GEMM: out[m,n] = sum_k A[m,k]*Bm[n,k] ----------------
// Block tile 128x64, BK=16, 8 warps (4x2), warp tile 32x32 (2x4 m16n8 frags).
// EPI==0 : out = sigmoid(acc) * tanh(cells)   (s_t path, exact tiles, ld=HDIM)
// EPI==1 : out[m*ldout+n] = acc, guarded by Mreal/Nreal
template<int EPI>
__global__ void __launch_bounds__(256, 2)
gemm_tf32_kernel(const float* __restrict__ A, const float* __restrict__ Bm,
                 const float* __restrict__ cells, float* __restrict__ out,
                 int Mreal, int Nreal, int ldout)
{
    __shared__ __align__(16) float As[128][20];  // stride 20 -> conflict-free frags
    __shared__ __align__(16) float Bs[64][20];

    const int tid  = threadIdx.x;
    const int lane = tid & 31;
    const int warp = tid >> 5;
    const int grp  = lane >> 2;     // 0..7
    const int qid  = lane & 3;      // 0..3
    const int wm   = warp >> 1;     // 0..3
    const int wn   = warp & 1;      // 0..1

    const int m0 = blockIdx.y * 128;
    const int n0 = blockIdx.x * 64;

    const int lrow = tid >> 2;      // 0..63
    const int lq   = tid & 3;

    float c[2][4][4];
    #pragma unroll
    for (int i = 0; i < 2; i++)
        #pragma unroll
        for (int j = 0; j < 4; j++)
            #pragma unroll
            for (int r = 0; r < 4; r++) c[i][j][r] = 0.f;

    for (int k0 = 0; k0 < HDIM; k0 += 16) {
        // ---- global -> smem (convert to tf32 once) ----
        #pragma unroll
        for (int half = 0; half < 2; half++) {
            int r = lrow + half * 64;
            int m = m0 + r;
            float4 v = make_float4(0.f, 0.f, 0.f, 0.f);
            if (m < Mreal)
                v = *(const float4*)(A + (size_t)m * HDIM + k0 + lq * 4);
            unsigned* dst = (unsigned*)&As[r][lq * 4];
            dst[0] = f2tf32(v.x); dst[1] = f2tf32(v.y);
            dst[2] = f2tf32(v.z); dst[3] = f2tf32(v.w);
        }
        {
            int n = n0 + lrow;
            float4 v = make_float4(0.f, 0.f, 0.f, 0.f);
            if (n < Nreal)
                v = *(const float4*)(Bm + (size_t)n * HDIM + k0 + lq * 4);
            unsigned* dst = (unsigned*)&Bs[lrow][lq * 4];
            dst[0] = f2tf32(v.x); dst[1] = f2tf32(v.y);
            dst[2] = f2tf32(v.z); dst[3] = f2tf32(v.w);
        }
        __syncthreads();

        // ---- two k8 steps ----
        #pragma unroll
        for (int kk = 0; kk < 2; kk++) {
            unsigned a[2][4], b[4][2];
            #pragma unroll
            for (int mt = 0; mt < 2; mt++) {
                int rb = wm * 32 + mt * 16 + grp;
                a[mt][0] = __float_as_uint(As[rb    ][kk * 8 + qid    ]);
                a[mt][1] = __float_as_uint(As[rb + 8][kk * 8 + qid    ]);
                a[mt][2] = __float_as_uint(As[rb    ][kk * 8 + qid + 4]);
                a[mt][3] = __float_as_uint(As[rb + 8][kk * 8 + qid + 4]);
            }
            #pragma unroll
            for (int nt = 0; nt < 4; nt++) {
                int nb = wn * 32 + nt * 8 + grp;
                b[nt][0] = __float_as_uint(Bs[nb][kk * 8 + qid    ]);
                b[nt][1] = __float_as_uint(Bs[nb][kk * 8 + qid + 4]);
            }
            #pragma unroll
            for (int mt = 0; mt < 2; mt++)
                #pragma unroll
                for (int nt = 0; nt < 4; nt++)
                    mma_tf32(c[mt][nt], a[mt][0], a[mt][1], a[mt][2], a[mt][3],
                             b[nt][0], b[nt][1]);
        }
        __syncthreads();
    }

    // ---- epilogue ----
    #pragma unroll
    for (int mt = 0; mt < 2; mt++) {
        #pragma unroll
        for (int nt = 0; nt < 4; nt++) {
            int m = m0 + wm * 32 + mt * 16 + grp;
            int n = n0 + wn * 32 + nt * 8 + qid * 2;
            #pragma unroll
            for (int half = 0; half < 2; half++) {
                int mm = m + half * 8;
                float v0 = c[mt][nt][half * 2 + 0];
                float v1 = c[mt][nt][half * 2 + 1];
                if (EPI == 0) {
                    size_t idx = (size_t)mm * HDIM + n;
                    float2 cl = *(const float2*)(cells + idx);
                    float s0 = 1.f / (1.f + expf(-v0));
                    float s1 = 1.f / (1.f + expf(-v1));
                    float2 o;
                    o.x = s0 * tanhf(cl.x);
                    o.y = s1 * tanhf(cl.y);
                    *(float2*)(out + idx) = o;
                } else {
                    if (mm < Mreal) {
                        size_t row = (size_t)mm * ldout;
                        if (n     < Nreal) out[row + n    ] = v0;
                        if (n + 1 < Nreal) out[row + n + 1] = v1;
                    }
                }
            }
        }
    }
}

// ---------------- attention logits: alpha, beta per (b,t) ----------------
__global__ void __launch_bounds__(64)
attn_logits_kernel(const float* __restrict__ Wh)
{
    const int t  = blockIdx.x;
    const int b  = blockIdx.y;
    const int bt = b * TDIM + t;
    const int tid = threadIdx.x;

    __shared__ float cvsh[KQ * KQ];
    __shared__ float gsh[KQ], cssh[KQ], whsh[64];
    __shared__ float zsh[64], red[64];

    for (int i = tid; i < KQ * KQ; i += 64) {
        int k = i / KQ, j = i - k * KQ;
        cvsh[i] = g_cv[(size_t)(b * KQ + k) * 64 + j];
    }
    if (tid < KQ) {
        gsh[tid]  = g_g [(size_t)bt * 64 + tid];
        cssh[tid] = g_cs[(size_t)bt * 64 + tid];
    }
    whsh[tid] = (tid < KQ) ? Wh[tid] : 0.f;
    __syncthreads();

    // z_ext = sum_j tanh(cs_j + g_j) * Wh_j
    float e = 0.f;
    if (tid < KQ) e = tanhf(cssh[tid] + gsh[tid]) * whsh[tid];
    red[tid] = e;
    __syncthreads();
    for (int s = 32; s > 0; s >>= 1) {
        if (tid < s) red[tid] += red[tid + s];
        __syncthreads();
    }
    float zx = red[0];
    __syncthreads();

    // z_k = sum_j tanh(cv[b,k,j] + g_j) * Wh_j
    float z = -1e30f;
    if (tid < KQ) {
        float acc = 0.f;
        const float* cvr = &cvsh[tid * KQ];
        #pragma unroll 7
        for (int j = 0; j < KQ; j++)
            acc += tanhf(cvr[j] + gsh[j]) * whsh[j];
        z = acc;
    }
    zsh[tid] = z;
    red[tid] = z;
    __syncthreads();
    for (int s = 32; s > 0; s >>= 1) {
        if (tid < s) red[tid] = fmaxf(red[tid], red[tid + s]);
        __syncthreads();
    }
    float mx = red[0];
    __syncthreads();

    float ez = (tid < KQ) ? expf(zsh[tid] - mx) : 0.f;
    red[tid] = ez;
    __syncthreads();
    for (int s = 32; s > 0; s >>= 1) {
        if (tid < s) red[tid] += red[tid + s];
        __syncthreads();
    }
    float sum49 = red[0];

    if (tid < KQ) g_al[(size_t)bt * 64 + tid] = ez / sum49;
    if (tid == 0) {
        float M2 = fmaxf(mx, zx);
        float denom = expf(mx - M2) * sum49 + expf(zx - M2);
        g_be[bt] = expf(zx - M2) / denom;
    }
}

// ---------------- final: out = beta*s_t + (1-beta)*(alpha@V) + hiddens ------
__global__ void __launch_bounds__(256)
final_kernel(const float* __restrict__ V, const float* __restrict__ hiddens,
             float* __restrict__ out)
{
    const int b  = blockIdx.z;
    const int t0 = blockIdx.y * 16;
    const int h0 = blockIdx.x * 256;
    const int tid  = threadIdx.x;
    const int hthr = tid & 63;      // 64 h-groups of 4
    const int tthr = tid >> 6;      // 4 t-groups of 4

    __shared__ float al[16][52];
    __shared__ float be[16];

    for (int i = tid; i < 16 * KQ; i += 256) {
        int tt = i / KQ, k = i - tt * KQ;
        al[tt][k] = g_al[(size_t)(b * TDIM + t0 + tt) * 64 + k];
    }
    if (tid < 16) be[tid] = g_be[b * TDIM + t0 + tid];
    __syncthreads();

    const int h = h0 + hthr * 4;
    float4 acc[4];
    #pragma unroll
    for (int i = 0; i < 4; i++) acc[i] = make_float4(0.f, 0.f, 0.f, 0.f);

    const float* Vb = V + (size_t)b * KQ * HDIM + h;
    for (int k = 0; k < KQ; k++) {
        float4 v = *(const float4*)(Vb + (size_t)k * HDIM);
        #pragma unroll
        for (int i = 0; i < 4; i++) {
            float a = al[tthr * 4 + i][k];
            acc[i].x += a * v.x; acc[i].y += a * v.y;
            acc[i].z += a * v.z; acc[i].w += a * v.w;
        }
    }
    #pragma unroll
    for (int i = 0; i < 4; i++) {
        int t = t0 + tthr * 4 + i;
        size_t idx = ((size_t)(b * TDIM + t)) * HDIM + h;
        float4 s  = *(const float4*)(g_st + idx);
        float4 hd = *(const float4*)(hiddens + idx);
        float bt = be[tthr * 4 + i];
        float om = 1.f - bt;
        float4 o;
        o.x = bt * s.x + om * acc[i].x + hd.x;
        o.y = bt * s.y + om * acc[i].y + hd.y;
        o.z = bt * s.z + om * acc[i].z + hd.z;
        o.w = bt * s.w + om * acc[i].w + hd.w;
        *(float4*)(out + idx) = o;
    }
}

// ---------------- launch ----------------
extern "C" void kernel_launch(void* const* d_in, const int* in_sizes, int n_in,
                              void* d_out, int out_size)
{
    const float* x       = (const float*)d_in[0];
    const float* hiddens = (const float*)d_in[1];
    const float* cells   = (const float*)d_in[2];
    const float* V       = (const float*)d_in[3];
    const float* Wx      = (const float*)d_in[4];
    // d_in[5] = Whh, unused: h_prev == 0 so its contribution is exactly zero.
    const float* Wv      = (const float*)d_in[6];
    const float* Wg      = (const float*)d_in[7];
    const float* Ws      = (const float*)d_in[8];
    const float* Wh      = (const float*)d_in[9];
    float* out = (float*)d_out;

    float *p_st, *p_g, *p_cs, *p_cv;
    cudaGetSymbolAddress((void**)&p_st, g_st);
    cudaGetSymbolAddress((void**)&p_g,  g_g);
    cudaGetSymbolAddress((void**)&p_cs, g_cs);
    cudaGetSymbolAddress((void**)&p_cv, g_cv);

    // s_t = sigmoid(x @ Wx^T) * tanh(cells)       [32768 x 1024]
    gemm_tf32_kernel<0><<<dim3(16, 256), 256>>>(x, Wx, cells, p_st,
                                                MT_ROWS, HDIM, HDIM);
    // g = hiddens @ Wg^T                          [32768 x 49]
    gemm_tf32_kernel<1><<<dim3(1, 256), 256>>>(hiddens, Wg, nullptr, p_g,
                                               MT_ROWS, KQ, 64);
    // cs = s_t @ Ws^T                             [32768 x 49] (after s_t)
    gemm_tf32_kernel<1><<<dim3(1, 256), 256>>>(p_st, Ws, nullptr, p_cs,
                                               MT_ROWS, KQ, 64);
    // cv = V @ Wv^T  (V viewed as [B*49, 1024])   [3136 x 49]
    gemm_tf32_kernel<1><<<dim3(1, 25), 256>>>(V, Wv, nullptr, p_cv,
                                              3136, KQ, 64);
    // alpha / beta per (b,t)
    attn_logits_kernel<<<dim3(TDIM, BDIM), 64>>>(Wh);
    // out = beta*s_t + (1-beta)*(alpha@V) + hiddens
    final_kernel<<<dim3(4, 32, 64), 256>>>(V, hiddens, out);
}